// round 17
// baseline (speedup 1.0000x reference)
#include <cuda_runtime.h>
#include <cuda_bf16.h>
#include <cuda_fp16.h>
#include <cstdint>

#define NB  4
#define NS  2048
#define ND  512
#define NH  8
#define NHD 64
#define NROWS (NB*NS)   // 8192
#define KST 72          // smem row stride (144B) — ldmatrix conflict-free
#define EX2C 0.18033688f // 0.125 * log2(e)

// ---------------- device-global scratch (all fp16) --------------------------
__device__ __half g_Af16[3ull*NROWS*ND];      // X,Y,Z fp16
__device__ __half g_WTf16[3ull*ND*ND];        // Wq^T, Wk^T, Wo^T fp16
__device__ __half g_Qf16[(size_t)NROWS*ND];   // [B,H,S,64]
__device__ __half g_Kf16[(size_t)NROWS*ND];
__device__ __half g_Vf16[(size_t)NROWS*ND];
__device__ __half g_Of16[(size_t)NROWS*ND];   // merged [B,S,D]
__device__ float  g_Vsum[NB*NH*NHD];

// ---------------- helpers ----------------------------------------------------
__device__ __forceinline__ void mma16816h(float c[4], const uint32_t a[4], const uint32_t b[2]) {
    asm volatile("mma.sync.aligned.m16n8k16.row.col.f32.f16.f16.f32 "
        "{%0,%1,%2,%3}, {%4,%5,%6,%7}, {%8,%9}, {%0,%1,%2,%3};"
        : "+f"(c[0]), "+f"(c[1]), "+f"(c[2]), "+f"(c[3])
        : "r"(a[0]), "r"(a[1]), "r"(a[2]), "r"(a[3]), "r"(b[0]), "r"(b[1]));
}
__device__ __forceinline__ uint32_t packh(float x, float y) {
    __half2 h = __floats2half2_rn(x, y);
    return *(uint32_t*)&h;
}
__device__ __forceinline__ uint32_t smem_u32(const void* p) {
    uint32_t a;
    asm("{ .reg .u64 t; cvta.to.shared.u64 t, %1; cvt.u32.u64 %0, t; }" : "=r"(a) : "l"(p));
    return a;
}
__device__ __forceinline__ void ldsm4(uint32_t r[4], uint32_t addr) {
    asm volatile("ldmatrix.sync.aligned.m8n8.x4.shared.b16 {%0,%1,%2,%3}, [%4];"
        : "=r"(r[0]), "=r"(r[1]), "=r"(r[2]), "=r"(r[3]) : "r"(addr));
}
__device__ __forceinline__ void ldsm4t(uint32_t r[4], uint32_t addr) {
    asm volatile("ldmatrix.sync.aligned.m8n8.x4.trans.shared.b16 {%0,%1,%2,%3}, [%4];"
        : "=r"(r[0]), "=r"(r[1]), "=r"(r[2]), "=r"(r[3]) : "r"(addr));
}
#define CPA(sd, gs) \
    asm volatile("cp.async.cg.shared.global [%0], [%1], 16;" :: "r"(sd), "l"(gs) : "memory")
#define CPCOMMIT() asm volatile("cp.async.commit_group;" ::: "memory")
#define CPWAIT(n)  asm volatile("cp.async.wait_group %0;" :: "n"(n) : "memory")

// ---------------- converts ---------------------------------------------------
__global__ __launch_bounds__(256) void convert_act(
    const float4* __restrict__ srcA, const float4* __restrict__ srcB, int whichA, int whichB)
{
    size_t i = (size_t)blockIdx.x * 256 + threadIdx.x;
    const float4* src = (blockIdx.y == 0) ? srcA : srcB;
    int which = (blockIdx.y == 0) ? whichA : whichB;
    __half* dst = g_Af16 + (size_t)which*NROWS*ND;
    float4 v = src[i];
    ushort2 a, b;
    *(uint32_t*)&a = packh(v.x, v.y);
    *(uint32_t*)&b = packh(v.z, v.w);
    *(ushort4*)((unsigned short*)dst + 4*i) = make_ushort4(a.x, a.y, b.x, b.y);
}
__global__ __launch_bounds__(256) void convert_wt(
    const float* __restrict__ Wq, const float* __restrict__ Wk, const float* __restrict__ Wo)
{
    __shared__ float tile[32][33];
    const int z = blockIdx.z;
    const float* W = (z == 0) ? Wq : (z == 1) ? Wk : Wo;
    const int tx = threadIdx.x & 31, ty = threadIdx.x >> 5;
    const int x0 = blockIdx.x * 32, y0 = blockIdx.y * 32;
    #pragma unroll
    for (int i = ty; i < 32; i += 8)
        tile[i][tx] = W[(size_t)(y0 + i) * ND + x0 + tx];
    __syncthreads();
    __half* dst = g_WTf16 + (size_t)z*ND*ND;
    #pragma unroll
    for (int i = ty; i < 32; i += 8)
        dst[(size_t)(x0 + i) * ND + y0 + tx] = __float2half_rn(tile[tx][i]);
}

__global__ __launch_bounds__(256) void vsum_kernel()
{
    __shared__ float acc[4][64];
    const int bh = blockIdx.x;
    const int d = threadIdx.x & 63, q = threadIdx.x >> 6;
    const __half* v = g_Vf16 + (size_t)bh*NS*NHD;
    float s = 0.f;
    for (int i = q*512; i < q*512 + 512; i++)
        s += __half2float(v[(size_t)i*NHD + d]);
    acc[q][d] = s;
    __syncthreads();
    if (q == 0)
        g_Vsum[bh*64 + d] = acc[0][d] + acc[1][d] + acc[2][d] + acc[3][d];
}

// ---------------- fp16 GEMM: C[8192,512] = A @ W -----------------------------
// 128x128 block tile, 8 warps (2m x 4n), k-chunks of 64 (8 barriers total),
// 3-stage cp.async ring. smem = 3 x 2 x 128 x 72 x 2 = 110592 -> 2 CTAs/SM.
#define GEMM_SMEM (3*2*128*KST*2)
__global__ __launch_bounds__(256, 2) void mma_gemm(float* __restrict__ outp, int mode)
{
    extern __shared__ __half smg[];
    const int t = threadIdx.x, w = t >> 5, lane = t & 31;
    const int g = lane >> 2, tg = lane & 3;
    const int G = lane >> 3, rr = lane & 7;
    const int wm = w >> 2, wn = w & 3;
    const int row0 = blockIdx.y * 128, col0 = blockIdx.x * 128;
    const int mat = blockIdx.z;
    const int lr = t >> 1, lh = t & 1;   // loader: row 0..127, 32-col half

    const __half* Ag = (mode == 0) ? g_Af16 + (size_t)mat*NROWS*ND : g_Of16;
    const __half* Wg = g_WTf16 + (size_t)((mode == 0) ? mat : 2)*ND*ND;

    const uint32_t smb = smem_u32(smg);
#define GARR(s, a) (smb + (uint32_t)(((s)*2 + (a)) * 128 * KST * 2))

#define GEMM_LOAD(k0, s) do {                                                   \
    const __half* _g0 = Ag + (size_t)(row0+lr)*ND + (k0) + lh*32;               \
    const __half* _g1 = Wg + (size_t)(col0+lr)*ND + (k0) + lh*32;               \
    uint32_t _sd = (uint32_t)(lr*KST + lh*32)*2;                                \
    _Pragma("unroll") for (int v = 0; v < 4; v++) {                             \
        CPA(GARR(s,0) + _sd + v*16, _g0 + v*8);                                 \
        CPA(GARR(s,1) + _sd + v*16, _g1 + v*8);                                 \
    } } while (0)

    float acc[4][4][4] = {};

    GEMM_LOAD(0, 0);  CPCOMMIT();
    GEMM_LOAD(64, 1); CPCOMMIT();

    for (int c = 0; c < 8; c++) {
        const int s = c % 3;
        if (c < 7) CPWAIT(1); else CPWAIT(0);
        __syncthreads();                        // chunk c resident; stage (c-1)%3 free
        if (c + 2 < 8) { GEMM_LOAD((c+2)*64, (c+2) % 3); CPCOMMIT(); }

        #pragma unroll
        for (int kf = 0; kf < 4; kf++) {
            uint32_t ah[4][4];
            #pragma unroll
            for (int mf = 0; mf < 4; mf++) {
                uint32_t r = wm*64 + mf*16 + (G & 1)*8 + rr;
                uint32_t cc = kf*16 + (G >> 1)*8;
                ldsm4(ah[mf], GARR(s,0) + (r*KST + cc)*2);
            }
            uint32_t bv[2][4];
            #pragma unroll
            for (int n2 = 0; n2 < 2; n2++) {
                uint32_t r = wn*32 + n2*16 + (G >> 1)*8 + rr;
                uint32_t cc = kf*16 + (G & 1)*8;
                ldsm4(bv[n2], GARR(s,1) + (r*KST + cc)*2);
            }
            #pragma unroll
            for (int mf = 0; mf < 4; mf++)
                #pragma unroll
                for (int nf = 0; nf < 4; nf++)
                    mma16816h(acc[mf][nf], ah[mf], &bv[nf>>1][(nf&1)*2]);
        }
    }

    #pragma unroll
    for (int mf = 0; mf < 4; mf++)
        #pragma unroll
        for (int nf = 0; nf < 4; nf++) {
            const int cc = col0 + wn*32 + nf*8 + tg*2;
            #pragma unroll
            for (int rr2 = 0; rr2 < 2; rr2++) {
                const int r = row0 + wm*64 + mf*16 + g + rr2*8;
                float x0 = acc[mf][nf][rr2*2], x1 = acc[mf][nf][rr2*2+1];
                if (mode == 0) {
                    int b = r >> 11, sN = r & 2047, h = cc >> 6, d = cc & 63;
                    size_t idx = (((size_t)(b*NH + h))*NS + sN)*NHD + d;
                    uint32_t p = packh(x0, x1);
                    if (mat == 0)      *(uint32_t*)&g_Qf16[idx] = p;
                    else if (mat == 1) *(uint32_t*)&g_Kf16[idx] = p;
                    else               *(uint32_t*)&g_Vf16[idx] = p;
                } else {
                    *(float2*)&outp[(size_t)r*ND + cc] = make_float2(x0, x1);
                }
            }
        }
}

// ---------------- attention: 6-stage ring, 2 tiles per barrier ---------------
// O_unnorm = Vsum(fp32) + P'@V, P' = exp2(max(s*EX2C,0)) - 1.
// smem: 6 stages x 2 arrays (K,V) x 64 x KST x 2 = 110592 -> 2 CTAs/SM.
#define ATTN_SMEM (6*2*64*KST*2)
__global__ __launch_bounds__(256, 2) void attn_kernel()
{
    extern __shared__ __half smh[];
    const int t = threadIdx.x, w = t >> 5, lane = t & 31;
    const int g = lane >> 2, tg = lane & 3;
    const int G = lane >> 3, rr = lane & 7;
    const int bh = blockIdx.y, q0 = blockIdx.x * 128;
    const size_t base = (size_t)bh * NS * NHD;
    const int alr = t >> 2, alc = (t & 3) * 16;

    const uint32_t smb = smem_u32(smh);
#define AARR(s, a) (smb + (uint32_t)(((s)*2 + (a)) * 64 * KST * 2))

#define ATTN_LOAD(j0, s) do {                                                   \
    const __half* _g0 = g_Kf16 + base + (size_t)((j0)+alr)*NHD + alc;           \
    const __half* _g1 = g_Vf16 + base + (size_t)((j0)+alr)*NHD + alc;           \
    uint32_t _sd = (uint32_t)(alr*KST + alc)*2;                                 \
    CPA(AARR(s,0) + _sd,      _g0);     CPA(AARR(s,0) + _sd + 16, _g0 + 8);     \
    CPA(AARR(s,1) + _sd,      _g1);     CPA(AARR(s,1) + _sd + 16, _g1 + 8);     \
    } while (0)

    float oacc[8][4] = {};
    float lsA[2][2] = {};

    // ---- stage Q (128 rows fp16) through stage-0 arrays, extract frags -----
    {
        const int qlr = t >> 1, qlh = t & 1;
        const __half* q_g = g_Qf16 + base + (size_t)(q0+qlr)*NHD + qlh*32;
        uint32_t qd = AARR(0, qlr>>6) + (uint32_t)((qlr&63)*KST + qlh*32)*2;
        #pragma unroll
        for (int v = 0; v < 4; v++) CPA(qd + v*16, q_g + v*8);
        CPCOMMIT();
    }
    CPWAIT(0);
    __syncthreads();

    uint32_t qf[4][4];
    {
        const uint32_t r = w*16 + (G & 1)*8 + rr;
        const uint32_t arr = r >> 6, ir = r & 63;
        #pragma unroll
        for (int kf = 0; kf < 4; kf++) {
            uint32_t cc = kf*16 + (G >> 1)*8;
            ldsm4(qf[kf], AARR(0, arr) + (ir*KST + cc)*2);
        }
    }
    __syncthreads();   // all warps done reading Q; stages 0/1 reusable

    // prologue: tiles 0..3 into stages 0..3, two tiles per commit group
    ATTN_LOAD(0,   0); ATTN_LOAD(64,  1); CPCOMMIT();
    ATTN_LOAD(128, 2); ATTN_LOAD(192, 3); CPCOMMIT();

// one 64-row k-tile: S = Q@K^T, P' = exp2(...)-1, O += P'@V
#define PROC_TILE(sx) do {                                                      \
    float c[8][4] = {};                                                         \
    _Pragma("unroll")                                                           \
    for (int kf = 0; kf < 4; kf++) {                                            \
        _Pragma("unroll")                                                       \
        for (int n2 = 0; n2 < 4; n2++) {                                        \
            uint32_t brow = n2*16 + (G >> 1)*8 + rr;                            \
            uint32_t bcol = kf*16 + (G & 1)*8;                                  \
            uint32_t kb[4];                                                     \
            ldsm4(kb, AARR(sx,0) + (brow*KST + bcol)*2);                        \
            mma16816h(c[n2*2],   qf[kf], &kb[0]);                               \
            mma16816h(c[n2*2+1], qf[kf], &kb[2]);                               \
        }                                                                       \
    }                                                                           \
    _Pragma("unroll")                                                           \
    for (int nf = 0; nf < 8; nf++)                                              \
        _Pragma("unroll")                                                       \
        for (int i = 0; i < 4; i++) {                                           \
            float p = exp2f(fmaxf(c[nf][i]*EX2C, 0.f)) - 1.0f;                  \
            c[nf][i] = p;                                                       \
            lsA[i>>1][nf&1] += p;                                               \
        }                                                                       \
    uint32_t pf[4][4];                                                          \
    _Pragma("unroll")                                                           \
    for (int kq = 0; kq < 4; kq++)                                              \
        _Pragma("unroll")                                                       \
        for (int half = 0; half < 2; half++) {                                  \
            const float* cv = c[2*kq + half];                                   \
            pf[kq][2*half+0] = packh(cv[0], cv[1]);                             \
            pf[kq][2*half+1] = packh(cv[2], cv[3]);                             \
        }                                                                       \
    _Pragma("unroll")                                                           \
    for (int kq = 0; kq < 4; kq++) {                                            \
        _Pragma("unroll")                                                       \
        for (int d2 = 0; d2 < 4; d2++) {                                        \
            uint32_t vrow = kq*16 + (G & 1)*8 + rr;                             \
            uint32_t vcol = d2*16 + (G >> 1)*8;                                 \
            uint32_t vb[4];                                                     \
            ldsm4t(vb, AARR(sx,1) + (vrow*KST + vcol)*2);                       \
            mma16816h(oacc[d2*2],   pf[kq], &vb[0]);                            \
            mma16816h(oacc[d2*2+1], pf[kq], &vb[2]);                            \
        }                                                                       \
    } } while (0)

    for (int m = 0; m < 16; m++) {
        if (m < 15) CPWAIT(1); else CPWAIT(0);
        __syncthreads();                         // tiles 2m,2m+1 resident; stages of iter m-1 free
        if (m < 14) {                            // tiles 2m+4, 2m+5 -> stages freed at iter m-1
            ATTN_LOAD((2*m+4)*64, (2*m+4) % 6);
            ATTN_LOAD((2*m+5)*64, (2*m+5) % 6);
            CPCOMMIT();
        }
        const int s0 = (2*m) % 6, s1 = (2*m+1) % 6;
        PROC_TILE(s0);
        PROC_TILE(s1);
    }

    float lsum[2] = { lsA[0][0] + lsA[0][1], lsA[1][0] + lsA[1][1] };
    #pragma unroll
    for (int i = 0; i < 2; i++) {
        lsum[i] += __shfl_xor_sync(0xffffffffu, lsum[i], 1);
        lsum[i] += __shfl_xor_sync(0xffffffffu, lsum[i], 2);
    }
    const float inv0 = 1.f / (2048.f + lsum[0]);
    const float inv1 = 1.f / (2048.f + lsum[1]);

    const int b = bh >> 3, h = bh & 7;
    const float* vs = &g_Vsum[bh*64];
    #pragma unroll
    for (int nf = 0; nf < 8; nf++) {
        const int d = nf*8 + tg*2;
        const int col = h*NHD + d;
        const float2 v2 = *(const float2*)&vs[d];
        #pragma unroll
        for (int rr2 = 0; rr2 < 2; rr2++) {
            const int srow = q0 + w*16 + g + rr2*8;
            const float inv = rr2 ? inv1 : inv0;
            float x0 = (oacc[nf][rr2*2]   + v2.x) * inv;
            float x1 = (oacc[nf][rr2*2+1] + v2.y) * inv;
            size_t idx = ((size_t)(b*NS + srow))*ND + col;
            *(uint32_t*)&g_Of16[idx] = packh(x0, x1);
        }
    }
}

// ---------------------------------------------------------------------------
extern "C" void kernel_launch(void* const* d_in, const int* in_sizes, int n_in,
                              void* d_out, int out_size)
{
    const float* X  = (const float*)d_in[0];
    const float* Y  = (const float*)d_in[1];
    const float* Z  = (const float*)d_in[2];
    const float* Wq = (const float*)d_in[3];
    const float* Wk = (const float*)d_in[4];
    /* d_in[5] = Wv unused (reference uses Wo for V projection) */
    const float* Wo = (const float*)d_in[6];
    float* out = (float*)d_out;

    static bool attr_done = false;
    if (!attr_done) {
        cudaFuncSetAttribute(mma_gemm,    cudaFuncAttributeMaxDynamicSharedMemorySize, GEMM_SMEM);
        cudaFuncSetAttribute(attn_kernel, cudaFuncAttributeMaxDynamicSharedMemorySize, ATTN_SMEM);
        attr_done = true;
    }

    // launch order keeps attn_kernel at ncu index 5
    convert_wt<<<dim3(16, 16, 3), 256>>>(Wq, Wk, Wo);                          // 0
    convert_act<<<dim3(NROWS*ND/4/256, 2), 256>>>(
        (const float4*)X, (const float4*)Y, 0, 1);                            // 1
    convert_act<<<dim3(NROWS*ND/4/256, 1), 256>>>(
        (const float4*)Z, (const float4*)Z, 2, 2);                            // 2
    mma_gemm<<<dim3(4, 64, 3), 256, GEMM_SMEM>>>(nullptr, 0);                  // 3
    vsum_kernel<<<32, 256>>>();                                                // 4
    attn_kernel<<<dim3(16, 32), 256, ATTN_SMEM>>>();                           // 5 <- profiled
    mma_gemm<<<dim3(4, 64, 1), 256, GEMM_SMEM>>>(out, 1);                      // 6
}